// round 14
// baseline (speedup 1.0000x reference)
#include <cuda_runtime.h>
#include <cuda_bf16.h>
#include <cstdint>
#include <cstddef>

#define HID   768
#define HID2  1536
#define NLAB  64
#define NTOK  65536
#define NTILES 1536            // 512 m-tiles x 3 n-tiles
#define KT_SPLITS 12

#if defined(__CUDA_ARCH__) && (defined(__CUDA_ARCH_FEAT_SM103_ALL) || \
    defined(__CUDA_ARCH_FEAT_SM100_ALL) || defined(__CUDA_ARCH_SPECIFIC__))
#define USE_TC 1
#else
#define USE_TC 0
#endif

// ---------------- scratch (static device arrays; no runtime alloc) ----------------
__device__ __align__(16) float g_P[NLAB * HID];
__device__ __align__(16) float g_Pp[KT_SPLITS * NLAB * HID];
__device__ __align__(16) __nv_bfloat16 g_Bh[HID * HID];
__device__ __align__(16) __nv_bfloat16 g_Bl[HID * HID];
__device__ __align__(16) __nv_bfloat16 g_Ah[(size_t)NTOK * HID];   // 100.7 MB
__device__ __align__(16) __nv_bfloat16 g_Al[(size_t)NTOK * HID];   // 100.7 MB

// ---------------- portable helpers ----------------
__device__ __forceinline__ uint32_t smem_u32(const void* p) {
    uint32_t a;
    asm("{ .reg .u64 t; cvta.to.shared.u64 t, %1; cvt.u32.u64 %0, t; }" : "=r"(a) : "l"(p));
    return a;
}
__device__ __forceinline__ float to_tf32(float x) {
    uint32_t u;
    asm("cvt.rna.tf32.f32 %0, %1;" : "=r"(u) : "f"(x));
    return __uint_as_float(u);
}
__device__ __forceinline__ void mma_tf32(float d[4], const float a[4], const float b[2]) {
    asm volatile(
        "mma.sync.aligned.m16n8k8.row.col.f32.tf32.tf32.f32 "
        "{%0,%1,%2,%3}, {%4,%5,%6,%7}, {%8,%9}, {%0,%1,%2,%3};\n"
        : "+f"(d[0]), "+f"(d[1]), "+f"(d[2]), "+f"(d[3])
        : "r"(__float_as_uint(a[0])), "r"(__float_as_uint(a[1])),
          "r"(__float_as_uint(a[2])), "r"(__float_as_uint(a[3])),
          "r"(__float_as_uint(b[0])), "r"(__float_as_uint(b[1])));
}
__device__ __forceinline__ void split4(float4 v, uint2& h, uint2& l) {
    __nv_bfloat16 hx = __float2bfloat16(v.x), hy = __float2bfloat16(v.y);
    __nv_bfloat16 hz = __float2bfloat16(v.z), hw = __float2bfloat16(v.w);
    __nv_bfloat162 p0 = {hx, hy}, p1 = {hz, hw};
    h.x = *(uint32_t*)&p0; h.y = *(uint32_t*)&p1;
    __nv_bfloat162 q0 = {__float2bfloat16(v.x - __bfloat162float(hx)),
                         __float2bfloat16(v.y - __bfloat162float(hy))};
    __nv_bfloat162 q1 = {__float2bfloat16(v.z - __bfloat162float(hz)),
                         __float2bfloat16(v.w - __bfloat162float(hw))};
    l.x = *(uint32_t*)&q0; l.y = *(uint32_t*)&q1;
}

#define SW128(o) ((o) ^ (((o) >> 3) & 0x70))
#define CP_ASYNC16(dst, src) \
    asm volatile("cp.async.cg.shared.global [%0], [%1], 16;" :: "r"(dst), "l"(src) : "memory")
// Non-blocking completion: LSU arrives on the mbarrier when ALL prior cp.async
// of this thread have landed in SMEM. .noinc: the arrive is pre-counted in the
// barrier's init count (128 producer threads).
#define CP_ARRIVE_NOINC(mbar) \
    asm volatile("cp.async.mbarrier.arrive.noinc.shared.b64 [%0];" :: "r"(mbar) : "memory")

// ---------------- sm_103a-specific ----------------
#if USE_TC
__device__ __forceinline__ uint32_t elect_one() {
    uint32_t p;
    asm volatile("{ .reg .pred p; elect.sync _|p, 0xFFFFFFFF; selp.b32 %0, 1, 0, p; }" : "=r"(p));
    return p;
}
#define MBAR_INIT(a, n)  asm volatile("mbarrier.init.shared.b64 [%0], %1;" :: "r"(a), "r"((uint32_t)(n)) : "memory")
#define MBAR_ARRIVE(a)   asm volatile("mbarrier.arrive.shared.b64 _, [%0];" :: "r"(a) : "memory")
#define MBAR_WAIT(a, ph) do {                                                      \
    uint32_t _m = (a), _p = (ph), _d;                                              \
    asm volatile("{ .reg .pred p; mbarrier.try_wait.parity.acquire.cta.shared::cta.b64 p, [%1], %2; selp.b32 %0,1,0,p; }" \
        : "=r"(_d) : "r"(_m), "r"(_p) : "memory");                                 \
    if (!_d) {                                                                     \
        asm volatile("{ .reg .pred P1; WL_%=: mbarrier.try_wait.parity.acquire.cta.shared::cta.b64 P1, [%0], %1, 0x989680;" \
                     " @P1 bra.uni WD_%=; bra.uni WL_%=; WD_%=: }"                 \
                     :: "r"(_m), "r"(_p) : "memory");                              \
    } } while (0)
#define TC_ALLOC(sa, n)   asm volatile("tcgen05.alloc.cta_group::1.sync.aligned.shared::cta.b32 [%0], %1;" :: "r"(sa), "r"((uint32_t)(n)) : "memory")
#define TC_DEALLOC(t, n)  asm volatile("tcgen05.dealloc.cta_group::1.sync.aligned.b32 %0, %1;" :: "r"(t), "r"((uint32_t)(n)))
#define TC_RELINQ()       asm volatile("tcgen05.relinquish_alloc_permit.cta_group::1.sync.aligned;")
#define TC_COMMIT(a)      asm volatile("tcgen05.commit.cta_group::1.mbarrier::arrive::one.shared::cluster.b64 [%0];" :: "r"(a) : "memory")
#define TC_WAIT_LD()      asm volatile("tcgen05.wait::ld.sync.aligned;" ::: "memory")
#define TC_FENCE_AFTER()  asm volatile("tcgen05.fence::after_thread_sync;" ::: "memory")
#define FENCE_ASYNC()     asm volatile("fence.proxy.async.shared::cta;" ::: "memory")
#define LDTM_X32(r, t) \
    asm volatile("tcgen05.ld.sync.aligned.32x32b.x32.b32 " \
        "{%0,%1,%2,%3,%4,%5,%6,%7,%8,%9,%10,%11,%12,%13,%14,%15," \
        "%16,%17,%18,%19,%20,%21,%22,%23,%24,%25,%26,%27,%28,%29,%30,%31}, [%32];" \
        : "=r"((r)[0]),"=r"((r)[1]),"=r"((r)[2]),"=r"((r)[3]),"=r"((r)[4]),"=r"((r)[5]),"=r"((r)[6]),"=r"((r)[7]), \
          "=r"((r)[8]),"=r"((r)[9]),"=r"((r)[10]),"=r"((r)[11]),"=r"((r)[12]),"=r"((r)[13]),"=r"((r)[14]),"=r"((r)[15]), \
          "=r"((r)[16]),"=r"((r)[17]),"=r"((r)[18]),"=r"((r)[19]),"=r"((r)[20]),"=r"((r)[21]),"=r"((r)[22]),"=r"((r)[23]), \
          "=r"((r)[24]),"=r"((r)[25]),"=r"((r)[26]),"=r"((r)[27]),"=r"((r)[28]),"=r"((r)[29]),"=r"((r)[30]),"=r"((r)[31]) \
        : "r"(t))

static constexpr uint64_t DESC_BASE_SW128 =
    (uint64_t(2) << 61) | (uint64_t(1) << 46) | (uint64_t(64) << 32) | (uint64_t(1) << 16);
#define MK_DESC(a) (DESC_BASE_SW128 | ((uint64_t)((a) >> 4) & 0x3FFF))

static constexpr uint32_t IDESC_128x256 =
    (1u << 4) | (1u << 7) | (1u << 10) | ((256u / 8) << 17) | ((128u / 16) << 24);

__device__ __forceinline__ void mma_bf16_ss(uint32_t d_tmem, uint64_t a_desc,
                                            uint64_t b_desc, uint32_t en) {
    asm volatile(
        "{ .reg .pred p; setp.ne.u32 p, %4, 0;"
        " tcgen05.mma.cta_group::1.kind::f16 [%0], %1, %2, %3, {%5,%5,%5,%5}, p; }"
        :: "r"(d_tmem), "l"(a_desc), "l"(b_desc), "r"(IDESC_128x256),
           "r"(en), "r"(0u) : "memory");
}
#endif // USE_TC

// ---------------- prep: split tokens and W_left into bf16 hi/lo ----------------
__global__ __launch_bounds__(256) void asplit_kernel(const float* __restrict__ t) {
    size_t n = (size_t)blockIdx.x * 256 + threadIdx.x;    // over NTOK*HID/4
    float4 v = *(const float4*)(t + n * 4);
    uint2 h, l;
    split4(v, h, l);
    *(uint2*)(g_Ah + n * 4) = h;
    *(uint2*)(g_Al + n * 4) = l;
}

__global__ void bsplit_kernel(const float* __restrict__ W) {
    int n = blockIdx.x * 256 + threadIdx.x;
    int j = n / 192, k4 = (n % 192) * 4;
    float4 v = *(const float4*)(W + (size_t)j * HID2 + k4);
    uint2 h, l;
    split4(v, h, l);
    size_t o = (size_t)j * HID + k4;
    *(uint2*)(g_Bh + o) = h;
    *(uint2*)(g_Bl + o) = l;
}

// ---------------- P table (exact fp32, deterministic) ----------------
__global__ __launch_bounds__(256) void p_accum_kernel(
        const float* __restrict__ lf, const float* __restrict__ W) {
    __shared__ float lf_s[64][64];
    __shared__ float w_s[128][33];
    const int tid = threadIdx.x;
    const int j0 = blockIdx.x * 128, k0 = blockIdx.y * 64;
    #pragma unroll
    for (int i = 0; i < 4; i++) {
        int idx = tid + i * 256, r = idx >> 4, c = (idx & 15) * 4;
        *(float4*)&lf_s[r][c] = *(const float4*)(lf + (size_t)r * HID + k0 + c);
    }
    const int jq = tid & 31, lq = tid >> 5;
    float acc[8][4];
    #pragma unroll
    for (int i = 0; i < 8; i++)
        #pragma unroll
        for (int jj = 0; jj < 4; jj++) acc[i][jj] = 0.f;
    for (int kc = 0; kc < 64; kc += 32) {
        __syncthreads();
        #pragma unroll
        for (int i = 0; i < 4; i++) {
            int idx = tid + i * 256, r = idx >> 3, c = (idx & 7) * 4;
            const float* src = W + (size_t)(j0 + r) * HID2 + HID + k0 + kc + c;
            w_s[r][c] = src[0]; w_s[r][c+1] = src[1]; w_s[r][c+2] = src[2]; w_s[r][c+3] = src[3];
        }
        __syncthreads();
        #pragma unroll
        for (int kk = 0; kk < 32; kk++) {
            float wv[4], lv[8];
            #pragma unroll
            for (int jj = 0; jj < 4; jj++) wv[jj] = w_s[jq + 32 * jj][kk];
            #pragma unroll
            for (int i = 0; i < 8; i++) lv[i] = lf_s[lq * 8 + i][kc + kk];
            #pragma unroll
            for (int i = 0; i < 8; i++)
                #pragma unroll
                for (int jj = 0; jj < 4; jj++) acc[i][jj] += lv[i] * wv[jj];
        }
    }
    float* dst = g_Pp + (size_t)blockIdx.y * NLAB * HID;
    #pragma unroll
    for (int i = 0; i < 8; i++)
        #pragma unroll
        for (int jj = 0; jj < 4; jj++)
            dst[(size_t)(lq * 8 + i) * HID + j0 + jq + 32 * jj] = acc[i][jj];
}

__global__ void p_reduce_kernel(const float* __restrict__ merge_b) {
    int i = blockIdx.x * blockDim.x + threadIdx.x;
    if (i >= NLAB * HID) return;
    float s = merge_b[i % HID];
    #pragma unroll
    for (int t = 0; t < KT_SPLITS; t++) s += g_Pp[t * NLAB * HID + i];
    g_P[i] = s;
}

// ---------------------------------------------------------------------------
// Persistent main kernel, 148 CTAs x 288 threads, warp-specialized:
//   warps 0-3: epilogue; warps 4-7: producers (NON-BLOCKING cp.async +
//   cp.async.mbarrier.arrive.noinc); warp 8: MMA issuer (consumer-side
//   fence.proxy.async before MMAs).
// ---------------------------------------------------------------------------
#define STG_SZ 98304                  // Ah16K|Al16K|Bh32K|Bl32K
#define HDR    512
#define OFF_AH(s) (HDR + (s) * STG_SZ)
#define OFF_AL(s) (OFF_AH(s) + 16384)
#define OFF_BH(s) (OFF_AH(s) + 32768)
#define OFF_BL(s) (OFF_AH(s) + 65536)
#define EPS_OFF   (HDR + 2 * STG_SZ)             // 128 x 68 floats = 34816 B
#define SMEM_TOTAL (EPS_OFF + 128 * 68 * 4)      // 231936 B
#define MB_FULL(s)  (sb + 16 + (s) * 8)
#define MB_EMPTY(s) (sb + 32 + (s) * 8)
#define MB_DONE(p)  (sb + 48 + (p) * 8)
#define MB_EFREE(p) (sb + 64 + (p) * 8)

__global__ __launch_bounds__(288, 1)
void fm_main_kernel(const float* __restrict__ tokens,
                    const int* __restrict__ labels,
                    const float* __restrict__ W,
                    float* __restrict__ out) {
    extern __shared__ char smem[];
    const int tid = threadIdx.x, wid = tid >> 5, lane = tid & 31;
    const int bid = blockIdx.x;

#if USE_TC
    const uint32_t sb = smem_u32(smem);
    if (tid == 0) {
        MBAR_INIT(MB_FULL(0), 128);  MBAR_INIT(MB_FULL(1), 128);
        MBAR_INIT(MB_EMPTY(0), 1);   MBAR_INIT(MB_EMPTY(1), 1);
        MBAR_INIT(MB_DONE(0), 1);    MBAR_INIT(MB_DONE(1), 1);
        MBAR_INIT(MB_EFREE(0), 128); MBAR_INIT(MB_EFREE(1), 128);
    }
    if (wid == 8) { TC_ALLOC(sb, 512); TC_RELINQ(); }
    __syncthreads();
    uint32_t tmem;
    asm volatile("ld.shared.b32 %0, [%1];" : "=r"(tmem) : "r"(sb));

    if (wid == 8) {
        // =============== MMA issuer ===============
        int cc = 0;
        for (int it = 0; ; it++) {
            const int t = bid + it * 148;
            if (t >= NTILES) break;
            const uint32_t dtm = tmem + (it & 1) * 256;
            if (it >= 2) {
                MBAR_WAIT(MB_EFREE(it & 1), ((it >> 1) - 1) & 1);
                TC_FENCE_AFTER();
            }
            for (int c = 0; c < 12; c++, cc++) {
                const int s = cc & 1;
                MBAR_WAIT(MB_FULL(s), (cc >> 1) & 1);
                FENCE_ASYNC();   // make cp.async-landed SMEM visible to async proxy
                if (elect_one()) {
                    uint64_t ah = MK_DESC(sb + OFF_AH(s)), al = MK_DESC(sb + OFF_AL(s));
                    uint64_t bh = MK_DESC(sb + OFF_BH(s)), bl = MK_DESC(sb + OFF_BL(s));
                    #pragma unroll
                    for (int ks = 0; ks < 4; ks++) {
                        mma_bf16_ss(dtm, ah + 2 * ks, bh + 2 * ks, (c | ks) ? 1u : 0u);
                        mma_bf16_ss(dtm, ah + 2 * ks, bl + 2 * ks, 1u);
                        mma_bf16_ss(dtm, al + 2 * ks, bh + 2 * ks, 1u);
                    }
                    TC_COMMIT(MB_EMPTY(s));
                    if (c == 11) TC_COMMIT(MB_DONE(it & 1));
                }
            }
        }
    } else if (wid >= 4) {
        // ===== producers (128 threads): issue-and-go, zero blocking on memory =====
        const int pt = tid - 128;                 // 0..127
        uint32_t aoff[8], boff0[8], boff1[8];
        #pragma unroll
        for (int i = 0; i < 8; i++) {
            aoff[i]  = SW128((uint32_t)(pt * 128 + i * 16));
            boff0[i] = SW128((uint32_t)((2 * pt) * 128 + i * 16));
            boff1[i] = SW128((uint32_t)((2 * pt + 1) * 128 + i * 16));
        }
        int cc = 0;
        for (int it = 0; ; it++) {
            const int t = bid + it * 148;
            if (t >= NTILES) break;
            const int m0 = (t / 3) * 128, n0 = (t % 3) * 256;
            const char* ah = (const char*)(g_Ah + (size_t)(m0 + pt) * HID);
            const char* al = (const char*)(g_Al + (size_t)(m0 + pt) * HID);
            const char* bh0 = (const char*)(g_Bh + (size_t)(n0 + 2 * pt) * HID);
            const char* bl0 = (const char*)(g_Bl + (size_t)(n0 + 2 * pt) * HID);
            const char* bh1 = bh0 + HID * 2;
            const char* bl1 = bl0 + HID * 2;
            for (int c = 0; c < 12; c++, cc++) {
                const int s = cc & 1;
                const int kb = c * 128;           // byte offset: 64 bf16 per chunk
                if (cc >= 2) MBAR_WAIT(MB_EMPTY(s), ((cc >> 1) - 1) & 1);
                #pragma unroll
                for (int i = 0; i < 8; i++) {
                    CP_ASYNC16(sb + OFF_AH(s) + aoff[i],  ah  + kb + 16 * i);
                    CP_ASYNC16(sb + OFF_AL(s) + aoff[i],  al  + kb + 16 * i);
                    CP_ASYNC16(sb + OFF_BH(s) + boff0[i], bh0 + kb + 16 * i);
                    CP_ASYNC16(sb + OFF_BL(s) + boff0[i], bl0 + kb + 16 * i);
                    CP_ASYNC16(sb + OFF_BH(s) + boff1[i], bh1 + kb + 16 * i);
                    CP_ASYNC16(sb + OFF_BL(s) + boff1[i], bl1 + kb + 16 * i);
                }
                CP_ARRIVE_NOINC(MB_FULL(s));      // async arrive on completion
            }
        }
    } else {
        // =============== epilogue warps (128 threads) ===============
        float* eps = (float*)(smem + EPS_OFF);
        const int rh = lane >> 4, cf = lane & 15;         // 2 rows/pass, 16 f4-cols
        for (int ep = 0; ; ep++) {
            const int t = bid + ep * 148;
            if (t >= NTILES) break;
            const int pm0 = (t / 3) * 128, pn0 = (t % 3) * 256;
            const int pb = ep & 1;
            MBAR_WAIT(MB_DONE(pb), (ep >> 1) & 1);
            TC_FENCE_AFTER();
            const uint32_t dtm = tmem + pb * 256;
            #pragma unroll
            for (int hh = 0; hh < 4; hh++) {
                uint32_t d[64];
                LDTM_X32(d, dtm + hh * 64);
                LDTM_X32(d + 32, dtm + hh * 64 + 32);
                TC_WAIT_LD();
                float* er = eps + (wid * 32 + lane) * 68;
                #pragma unroll
                for (int j = 0; j < 32; j++)
                    *(uint2*)(er + 2 * j) = make_uint2(d[2 * j], d[2 * j + 1]);
                __syncwarp();
                #pragma unroll 4
                for (int p = 0; p < 16; p++) {
                    const int row = wid * 32 + p * 2 + rh;
                    const int lbl = labels[pm0 + row];
                    const size_t ro = (size_t)(pm0 + row) * HID + pn0 + hh * 64 + cf * 4;
                    if (lbl) {
                        float4 v = *(const float4*)(eps + row * 68 + cf * 4);
                        float4 pv = *(const float4*)(g_P + (size_t)(lbl - 1) * HID
                                                     + pn0 + hh * 64 + cf * 4);
                        float4 o = {v.x + pv.x, v.y + pv.y, v.z + pv.z, v.w + pv.w};
                        *(float4*)(out + ro) = o;
                    } else {
                        *(float4*)(out + ro) = *(const float4*)(tokens + ro);
                    }
                }
                __syncwarp();
            }
            MBAR_ARRIVE(MB_EFREE(pb));
        }
    }
    __syncthreads();
    if (wid == 8) TC_DEALLOC(tmem, 512);

#else  // ------------------- portable TF32 fallback (persistent) -------------------
    float (*As)[36] = (float(*)[36])(smem);
    float (*Bs)[36] = (float(*)[36])(smem + 128 * 36 * 4);
    int*   lbl_s    = (int*)(smem + 2 * 128 * 36 * 4);
    const int wm = wid >> 2, wn = wid & 3;

    for (int it = 0; ; it++) {
        const int t = bid + it * 148;
        if (t >= NTILES) break;
        const int m0 = (t / 3) * 128, base_n = (t % 3) * 256;
        __syncthreads();
        if (tid < 128) lbl_s[tid] = labels[m0 + tid];

        for (int nh = 0; nh < 2; nh++) {
            const int n0 = base_n + nh * 128;
            float acc[4][4][4];
            #pragma unroll
            for (int a = 0; a < 4; a++)
                #pragma unroll
                for (int b = 0; b < 4; b++)
                    #pragma unroll
                    for (int c = 0; c < 4; c++) acc[a][b][c] = 0.f;
            __syncthreads();

            for (int k0 = 0; k0 < HID; k0 += 32) {
                if (tid < 256) {
                    #pragma unroll
                    for (int i = 0; i < 4; i++) {
                        int idx = tid + i * 256;
                        int r = idx >> 3, c = (idx & 7) * 4;
                        float4 va = *(const float4*)(tokens + (size_t)(m0 + r) * HID + k0 + c);
                        va.x = to_tf32(va.x); va.y = to_tf32(va.y);
                        va.z = to_tf32(va.z); va.w = to_tf32(va.w);
                        *(float4*)&As[r][c] = va;
                        float4 vb = *(const float4*)(W + (size_t)(n0 + r) * HID2 + k0 + c);
                        vb.x = to_tf32(vb.x); vb.y = to_tf32(vb.y);
                        vb.z = to_tf32(vb.z); vb.w = to_tf32(vb.w);
                        *(float4*)&Bs[r][c] = vb;
                    }
                }
                __syncthreads();
                if (tid < 256) {
                    #pragma unroll
                    for (int ks = 0; ks < 4; ks++) {
                        const int cb = ks * 8 + (lane & 3);
                        float a[4][4], b[4][2];
                        #pragma unroll
                        for (int mi = 0; mi < 4; mi++) {
                            int r = wm * 64 + mi * 16 + (lane >> 2);
                            a[mi][0] = As[r][cb];     a[mi][1] = As[r + 8][cb];
                            a[mi][2] = As[r][cb + 4]; a[mi][3] = As[r + 8][cb + 4];
                        }
                        #pragma unroll
                        for (int ni = 0; ni < 4; ni++) {
                            int r = wn * 32 + ni * 8 + (lane >> 2);
                            b[ni][0] = Bs[r][cb]; b[ni][1] = Bs[r][cb + 4];
                        }
                        #pragma unroll
                        for (int mi = 0; mi < 4; mi++)
                            #pragma unroll
                            for (int ni = 0; ni < 4; ni++)
                                mma_tf32(acc[mi][ni], a[mi], b[ni]);
                    }
                }
                __syncthreads();
            }

            if (tid < 256) {
                const int gq = lane >> 2, tg = lane & 3;
                #pragma unroll
                for (int mi = 0; mi < 4; mi++) {
                    #pragma unroll
                    for (int half = 0; half < 2; half++) {
                        int r = wm * 64 + mi * 16 + gq + half * 8;
                        int lbl = lbl_s[r];
                        size_t rowOff = (size_t)(m0 + r) * HID;
                        #pragma unroll
                        for (int ni = 0; ni < 4; ni++) {
                            int gc = n0 + wn * 32 + ni * 8 + tg * 2;
                            float2 res;
                            if (lbl != 0) {
                                float2 p = *(const float2*)(&g_P[(size_t)(lbl - 1) * HID + gc]);
                                res.x = acc[mi][ni][half * 2 + 0] + p.x;
                                res.y = acc[mi][ni][half * 2 + 1] + p.y;
                            } else {
                                res = *(const float2*)(tokens + rowOff + gc);
                            }
                            *(float2*)(out + rowOff + gc) = res;
                        }
                    }
                }
            }
        }
    }
#endif
}

extern "C" void kernel_launch(void* const* d_in, const int* in_sizes, int n_in,
                              void* d_out, int out_size) {
    const float* com    = (const float*)d_in[0];   // [16,4096,768] f32
    const int*   labels = (const int*)d_in[1];     // [16,4096] int32
    const float* lf     = (const float*)d_in[2];   // [64,768] f32
    const float* mw     = (const float*)d_in[3];   // [768,1536] f32
    const float* mb     = (const float*)d_in[4];   // [768] f32
    float* out = (float*)d_out;

    cudaFuncSetAttribute(fm_main_kernel,
                         cudaFuncAttributeMaxDynamicSharedMemorySize, SMEM_TOTAL);

    asplit_kernel<<<(int)((size_t)NTOK * HID / 4 / 256), 256>>>(com);
    bsplit_kernel<<<576, 256>>>(mw);
    p_accum_kernel<<<dim3(6, KT_SPLITS), 256>>>(lf, mw);
    p_reduce_kernel<<<(NLAB * HID + 255) / 256, 256>>>(mb);
    fm_main_kernel<<<148, 288, SMEM_TOTAL>>>(com, labels, mw, out);
}

// round 16
// speedup vs baseline: 1.9714x; 1.9714x over previous
#include <cuda_runtime.h>
#include <cuda_bf16.h>
#include <cstdint>
#include <cstddef>

#define HID   768
#define HID2  1536
#define NLAB  64
#define NTOK  65536
#define NTILES 1536            // 512 m-tiles x 3 n-tiles
#define KT_SPLITS 12

#if defined(__CUDA_ARCH__) && (defined(__CUDA_ARCH_FEAT_SM103_ALL) || \
    defined(__CUDA_ARCH_FEAT_SM100_ALL) || defined(__CUDA_ARCH_SPECIFIC__))
#define USE_TC 1
#else
#define USE_TC 0
#endif

// ---------------- scratch (static device arrays; no runtime alloc) ----------------
__device__ __align__(16) float g_P[NLAB * HID];
__device__ __align__(16) float g_Pp[KT_SPLITS * NLAB * HID];
__device__ __align__(16) __nv_bfloat16 g_Bh[HID * HID];
__device__ __align__(16) __nv_bfloat16 g_Bl[HID * HID];
__device__ __align__(16) __nv_bfloat16 g_Ah[(size_t)NTOK * HID];   // 100.7 MB
__device__ __align__(16) __nv_bfloat16 g_Al[(size_t)NTOK * HID];   // 100.7 MB

// ---------------- portable helpers ----------------
__device__ __forceinline__ uint32_t smem_u32(const void* p) {
    uint32_t a;
    asm("{ .reg .u64 t; cvta.to.shared.u64 t, %1; cvt.u32.u64 %0, t; }" : "=r"(a) : "l"(p));
    return a;
}
__device__ __forceinline__ float to_tf32(float x) {
    uint32_t u;
    asm("cvt.rna.tf32.f32 %0, %1;" : "=r"(u) : "f"(x));
    return __uint_as_float(u);
}
__device__ __forceinline__ void mma_tf32(float d[4], const float a[4], const float b[2]) {
    asm volatile(
        "mma.sync.aligned.m16n8k8.row.col.f32.tf32.tf32.f32 "
        "{%0,%1,%2,%3}, {%4,%5,%6,%7}, {%8,%9}, {%0,%1,%2,%3};\n"
        : "+f"(d[0]), "+f"(d[1]), "+f"(d[2]), "+f"(d[3])
        : "r"(__float_as_uint(a[0])), "r"(__float_as_uint(a[1])),
          "r"(__float_as_uint(a[2])), "r"(__float_as_uint(a[3])),
          "r"(__float_as_uint(b[0])), "r"(__float_as_uint(b[1])));
}
__device__ __forceinline__ void split4(float4 v, uint2& h, uint2& l) {
    __nv_bfloat16 hx = __float2bfloat16(v.x), hy = __float2bfloat16(v.y);
    __nv_bfloat16 hz = __float2bfloat16(v.z), hw = __float2bfloat16(v.w);
    __nv_bfloat162 p0 = {hx, hy}, p1 = {hz, hw};
    h.x = *(uint32_t*)&p0; h.y = *(uint32_t*)&p1;
    __nv_bfloat162 q0 = {__float2bfloat16(v.x - __bfloat162float(hx)),
                         __float2bfloat16(v.y - __bfloat162float(hy))};
    __nv_bfloat162 q1 = {__float2bfloat16(v.z - __bfloat162float(hz)),
                         __float2bfloat16(v.w - __bfloat162float(hw))};
    l.x = *(uint32_t*)&q0; l.y = *(uint32_t*)&q1;
}

#define SW128(o) ((o) ^ (((o) >> 3) & 0x70))
#define CP_ASYNC16(dst, src) \
    asm volatile("cp.async.cg.shared.global [%0], [%1], 16;" :: "r"(dst), "l"(src) : "memory")
// Non-blocking completion: LSU arrives on the mbarrier when ALL prior cp.async
// of this thread have landed in SMEM. .noinc: arrive pre-counted in init count.
#define CP_ARRIVE_NOINC(mbar) \
    asm volatile("cp.async.mbarrier.arrive.noinc.shared.b64 [%0];" :: "r"(mbar) : "memory")

// ---------------- sm_103a-specific ----------------
#if USE_TC
__device__ __forceinline__ uint32_t elect_one() {
    uint32_t p;
    asm volatile("{ .reg .pred p; elect.sync _|p, 0xFFFFFFFF; selp.b32 %0, 1, 0, p; }" : "=r"(p));
    return p;
}
#define MBAR_INIT(a, n)  asm volatile("mbarrier.init.shared.b64 [%0], %1;" :: "r"(a), "r"((uint32_t)(n)) : "memory")
#define MBAR_ARRIVE(a)   asm volatile("mbarrier.arrive.shared.b64 _, [%0];" :: "r"(a) : "memory")
#define MBAR_WAIT(a, ph) do {                                                      \
    uint32_t _m = (a), _p = (ph), _d;                                              \
    asm volatile("{ .reg .pred p; mbarrier.try_wait.parity.acquire.cta.shared::cta.b64 p, [%1], %2; selp.b32 %0,1,0,p; }" \
        : "=r"(_d) : "r"(_m), "r"(_p) : "memory");                                 \
    if (!_d) {                                                                     \
        asm volatile("{ .reg .pred P1; WL_%=: mbarrier.try_wait.parity.acquire.cta.shared::cta.b64 P1, [%0], %1, 0x989680;" \
                     " @P1 bra.uni WD_%=; bra.uni WL_%=; WD_%=: }"                 \
                     :: "r"(_m), "r"(_p) : "memory");                              \
    } } while (0)
#define TC_ALLOC(sa, n)   asm volatile("tcgen05.alloc.cta_group::1.sync.aligned.shared::cta.b32 [%0], %1;" :: "r"(sa), "r"((uint32_t)(n)) : "memory")
#define TC_DEALLOC(t, n)  asm volatile("tcgen05.dealloc.cta_group::1.sync.aligned.b32 %0, %1;" :: "r"(t), "r"((uint32_t)(n)))
#define TC_RELINQ()       asm volatile("tcgen05.relinquish_alloc_permit.cta_group::1.sync.aligned;")
#define TC_COMMIT(a)      asm volatile("tcgen05.commit.cta_group::1.mbarrier::arrive::one.shared::cluster.b64 [%0];" :: "r"(a) : "memory")
#define TC_WAIT_LD()      asm volatile("tcgen05.wait::ld.sync.aligned;" ::: "memory")
#define TC_FENCE_AFTER()  asm volatile("tcgen05.fence::after_thread_sync;" ::: "memory")
#define FENCE_ASYNC()     asm volatile("fence.proxy.async.shared::cta;" ::: "memory")
#define LDTM_X32(r, t) \
    asm volatile("tcgen05.ld.sync.aligned.32x32b.x32.b32 " \
        "{%0,%1,%2,%3,%4,%5,%6,%7,%8,%9,%10,%11,%12,%13,%14,%15," \
        "%16,%17,%18,%19,%20,%21,%22,%23,%24,%25,%26,%27,%28,%29,%30,%31}, [%32];" \
        : "=r"((r)[0]),"=r"((r)[1]),"=r"((r)[2]),"=r"((r)[3]),"=r"((r)[4]),"=r"((r)[5]),"=r"((r)[6]),"=r"((r)[7]), \
          "=r"((r)[8]),"=r"((r)[9]),"=r"((r)[10]),"=r"((r)[11]),"=r"((r)[12]),"=r"((r)[13]),"=r"((r)[14]),"=r"((r)[15]), \
          "=r"((r)[16]),"=r"((r)[17]),"=r"((r)[18]),"=r"((r)[19]),"=r"((r)[20]),"=r"((r)[21]),"=r"((r)[22]),"=r"((r)[23]), \
          "=r"((r)[24]),"=r"((r)[25]),"=r"((r)[26]),"=r"((r)[27]),"=r"((r)[28]),"=r"((r)[29]),"=r"((r)[30]),"=r"((r)[31]) \
        : "r"(t))

static constexpr uint64_t DESC_BASE_SW128 =
    (uint64_t(2) << 61) | (uint64_t(1) << 46) | (uint64_t(64) << 32) | (uint64_t(1) << 16);
#define MK_DESC(a) (DESC_BASE_SW128 | ((uint64_t)((a) >> 4) & 0x3FFF))

static constexpr uint32_t IDESC_128x256 =
    (1u << 4) | (1u << 7) | (1u << 10) | ((256u / 8) << 17) | ((128u / 16) << 24);

__device__ __forceinline__ void mma_bf16_ss(uint32_t d_tmem, uint64_t a_desc,
                                            uint64_t b_desc, uint32_t en) {
    asm volatile(
        "{ .reg .pred p; setp.ne.u32 p, %4, 0;"
        " tcgen05.mma.cta_group::1.kind::f16 [%0], %1, %2, %3, {%5,%5,%5,%5}, p; }"
        :: "r"(d_tmem), "l"(a_desc), "l"(b_desc), "r"(IDESC_128x256),
           "r"(en), "r"(0u) : "memory");
}
#endif // USE_TC

// ---------------- prep: split tokens and W_left into bf16 hi/lo ----------------
__global__ __launch_bounds__(256) void asplit_kernel(const float* __restrict__ t) {
    size_t n = (size_t)blockIdx.x * 256 + threadIdx.x;    // over NTOK*HID/4
    float4 v = *(const float4*)(t + n * 4);
    uint2 h, l;
    split4(v, h, l);
    *(uint2*)(g_Ah + n * 4) = h;
    *(uint2*)(g_Al + n * 4) = l;
}

__global__ void bsplit_kernel(const float* __restrict__ W) {
    int n = blockIdx.x * 256 + threadIdx.x;
    int j = n / 192, k4 = (n % 192) * 4;
    float4 v = *(const float4*)(W + (size_t)j * HID2 + k4);
    uint2 h, l;
    split4(v, h, l);
    size_t o = (size_t)j * HID + k4;
    *(uint2*)(g_Bh + o) = h;
    *(uint2*)(g_Bl + o) = l;
}

// ---------------- P table (exact fp32, deterministic) ----------------
__global__ __launch_bounds__(256) void p_accum_kernel(
        const float* __restrict__ lf, const float* __restrict__ W) {
    __shared__ float lf_s[64][64];
    __shared__ float w_s[128][33];
    const int tid = threadIdx.x;
    const int j0 = blockIdx.x * 128, k0 = blockIdx.y * 64;
    #pragma unroll
    for (int i = 0; i < 4; i++) {
        int idx = tid + i * 256, r = idx >> 4, c = (idx & 15) * 4;
        *(float4*)&lf_s[r][c] = *(const float4*)(lf + (size_t)r * HID + k0 + c);
    }
    const int jq = tid & 31, lq = tid >> 5;
    float acc[8][4];
    #pragma unroll
    for (int i = 0; i < 8; i++)
        #pragma unroll
        for (int jj = 0; jj < 4; jj++) acc[i][jj] = 0.f;
    for (int kc = 0; kc < 64; kc += 32) {
        __syncthreads();
        #pragma unroll
        for (int i = 0; i < 4; i++) {
            int idx = tid + i * 256, r = idx >> 3, c = (idx & 7) * 4;
            const float* src = W + (size_t)(j0 + r) * HID2 + HID + k0 + kc + c;
            w_s[r][c] = src[0]; w_s[r][c+1] = src[1]; w_s[r][c+2] = src[2]; w_s[r][c+3] = src[3];
        }
        __syncthreads();
        #pragma unroll
        for (int kk = 0; kk < 32; kk++) {
            float wv[4], lv[8];
            #pragma unroll
            for (int jj = 0; jj < 4; jj++) wv[jj] = w_s[jq + 32 * jj][kk];
            #pragma unroll
            for (int i = 0; i < 8; i++) lv[i] = lf_s[lq * 8 + i][kc + kk];
            #pragma unroll
            for (int i = 0; i < 8; i++)
                #pragma unroll
                for (int jj = 0; jj < 4; jj++) acc[i][jj] += lv[i] * wv[jj];
        }
    }
    float* dst = g_Pp + (size_t)blockIdx.y * NLAB * HID;
    #pragma unroll
    for (int i = 0; i < 8; i++)
        #pragma unroll
        for (int jj = 0; jj < 4; jj++)
            dst[(size_t)(lq * 8 + i) * HID + j0 + jq + 32 * jj] = acc[i][jj];
}

__global__ void p_reduce_kernel(const float* __restrict__ merge_b) {
    int i = blockIdx.x * blockDim.x + threadIdx.x;
    if (i >= NLAB * HID) return;
    float s = merge_b[i % HID];
    #pragma unroll
    for (int t = 0; t < KT_SPLITS; t++) s += g_Pp[t * NLAB * HID + i];
    g_P[i] = s;
}

// ---------------------------------------------------------------------------
// Persistent main kernel, 148 CTAs x 288 threads, warp-specialized:
//   warps 0-3: epilogue; warps 4-7: producers — COALESCED cp.async
//   (lane -> 4-rows x 8-segs: 4 contiguous 128B lines per warp instruction,
//   nL=4 instead of 32); warp 8: MMA issuer.
// ---------------------------------------------------------------------------
#define STG_SZ 98304                  // Ah16K|Al16K|Bh32K|Bl32K
#define HDR    512
#define OFF_AH(s) (HDR + (s) * STG_SZ)
#define OFF_AL(s) (OFF_AH(s) + 16384)
#define OFF_BH(s) (OFF_AH(s) + 32768)
#define OFF_BL(s) (OFF_AH(s) + 65536)
#define EPS_OFF   (HDR + 2 * STG_SZ)             // 128 x 68 floats = 34816 B
#define SMEM_TOTAL (EPS_OFF + 128 * 68 * 4)      // 231936 B
#define MB_FULL(s)  (sb + 16 + (s) * 8)
#define MB_EMPTY(s) (sb + 32 + (s) * 8)
#define MB_DONE(p)  (sb + 48 + (p) * 8)
#define MB_EFREE(p) (sb + 64 + (p) * 8)

__global__ __launch_bounds__(288, 1)
void fm_main_kernel(const float* __restrict__ tokens,
                    const int* __restrict__ labels,
                    const float* __restrict__ W,
                    float* __restrict__ out) {
    extern __shared__ char smem[];
    const int tid = threadIdx.x, wid = tid >> 5, lane = tid & 31;
    const int bid = blockIdx.x;

#if USE_TC
    const uint32_t sb = smem_u32(smem);
    if (tid == 0) {
        MBAR_INIT(MB_FULL(0), 128);  MBAR_INIT(MB_FULL(1), 128);
        MBAR_INIT(MB_EMPTY(0), 1);   MBAR_INIT(MB_EMPTY(1), 1);
        MBAR_INIT(MB_DONE(0), 1);    MBAR_INIT(MB_DONE(1), 1);
        MBAR_INIT(MB_EFREE(0), 128); MBAR_INIT(MB_EFREE(1), 128);
    }
    if (wid == 8) { TC_ALLOC(sb, 512); TC_RELINQ(); }
    __syncthreads();
    uint32_t tmem;
    asm volatile("ld.shared.b32 %0, [%1];" : "=r"(tmem) : "r"(sb));

    if (wid == 8) {
        // =============== MMA issuer ===============
        int cc = 0;
        for (int it = 0; ; it++) {
            const int t = bid + it * 148;
            if (t >= NTILES) break;
            const uint32_t dtm = tmem + (it & 1) * 256;
            if (it >= 2) {
                MBAR_WAIT(MB_EFREE(it & 1), ((it >> 1) - 1) & 1);
                TC_FENCE_AFTER();
            }
            for (int c = 0; c < 12; c++, cc++) {
                const int s = cc & 1;
                MBAR_WAIT(MB_FULL(s), (cc >> 1) & 1);
                FENCE_ASYNC();   // cp.async-landed SMEM -> async proxy visibility
                if (elect_one()) {
                    uint64_t ah = MK_DESC(sb + OFF_AH(s)), al = MK_DESC(sb + OFF_AL(s));
                    uint64_t bh = MK_DESC(sb + OFF_BH(s)), bl = MK_DESC(sb + OFF_BL(s));
                    #pragma unroll
                    for (int ks = 0; ks < 4; ks++) {
                        mma_bf16_ss(dtm, ah + 2 * ks, bh + 2 * ks, (c | ks) ? 1u : 0u);
                        mma_bf16_ss(dtm, ah + 2 * ks, bl + 2 * ks, 1u);
                        mma_bf16_ss(dtm, al + 2 * ks, bh + 2 * ks, 1u);
                    }
                    TC_COMMIT(MB_EMPTY(s));
                    if (c == 11) TC_COMMIT(MB_DONE(it & 1));
                }
            }
        }
    } else if (wid >= 4) {
        // ====== producers (128 threads): COALESCED non-blocking cp.async ======
        // Warp instruction granularity: 4 rows x (8 lanes x 16B contiguous).
        const int pw = wid - 4;                    // 0..3
        const int rsub = lane >> 3, seg = lane & 7;
        uint32_t aoffs[8], boffs[16];
        #pragma unroll
        for (int j = 0; j < 8; j++)                // A: 32 rows per warp
            aoffs[j] = SW128((uint32_t)((pw * 32 + j * 4 + rsub) * 128 + seg * 16));
        #pragma unroll
        for (int j = 0; j < 16; j++)               // B: 64 rows per warp
            boffs[j] = SW128((uint32_t)((pw * 64 + j * 4 + rsub) * 128 + seg * 16));

        int cc = 0;
        for (int it = 0; ; it++) {
            const int t = bid + it * 148;
            if (t >= NTILES) break;
            const int m0 = (t / 3) * 128, n0 = (t % 3) * 256;
            // per-thread GMEM bases (row step = 4 rows = 4*1536 bytes)
            const char* ahb = (const char*)g_Ah + (size_t)(m0 + pw * 32 + rsub) * 1536 + seg * 16;
            const char* alb = (const char*)g_Al + (size_t)(m0 + pw * 32 + rsub) * 1536 + seg * 16;
            const char* bhb = (const char*)g_Bh + (size_t)(n0 + pw * 64 + rsub) * 1536 + seg * 16;
            const char* blb = (const char*)g_Bl + (size_t)(n0 + pw * 64 + rsub) * 1536 + seg * 16;
            for (int c = 0; c < 12; c++, cc++) {
                const int s = cc & 1;
                const int kb = c * 128;            // byte offset of K-chunk
                if (cc >= 2) MBAR_WAIT(MB_EMPTY(s), ((cc >> 1) - 1) & 1);
                #pragma unroll
                for (int j = 0; j < 8; j++) {
                    CP_ASYNC16(sb + OFF_AH(s) + aoffs[j], ahb + kb + (size_t)j * 6144);
                    CP_ASYNC16(sb + OFF_AL(s) + aoffs[j], alb + kb + (size_t)j * 6144);
                }
                #pragma unroll
                for (int j = 0; j < 16; j++) {
                    CP_ASYNC16(sb + OFF_BH(s) + boffs[j], bhb + kb + (size_t)j * 6144);
                    CP_ASYNC16(sb + OFF_BL(s) + boffs[j], blb + kb + (size_t)j * 6144);
                }
                CP_ARRIVE_NOINC(MB_FULL(s));       // async arrive on landing
            }
        }
    } else {
        // =============== epilogue warps (128 threads) ===============
        float* eps = (float*)(smem + EPS_OFF);
        const int rh = lane >> 4, cf = lane & 15;         // 2 rows/pass, 16 f4-cols
        for (int ep = 0; ; ep++) {
            const int t = bid + ep * 148;
            if (t >= NTILES) break;
            const int pm0 = (t / 3) * 128, pn0 = (t % 3) * 256;
            const int pb = ep & 1;
            MBAR_WAIT(MB_DONE(pb), (ep >> 1) & 1);
            TC_FENCE_AFTER();
            const uint32_t dtm = tmem + pb * 256;
            #pragma unroll
            for (int hh = 0; hh < 4; hh++) {
                uint32_t d[64];
                LDTM_X32(d, dtm + hh * 64);
                LDTM_X32(d + 32, dtm + hh * 64 + 32);
                TC_WAIT_LD();
                float* er = eps + (wid * 32 + lane) * 68;
                #pragma unroll
                for (int j = 0; j < 32; j++)
                    *(uint2*)(er + 2 * j) = make_uint2(d[2 * j], d[2 * j + 1]);
                __syncwarp();
                #pragma unroll 4
                for (int p = 0; p < 16; p++) {
                    const int row = wid * 32 + p * 2 + rh;
                    const int lbl = labels[pm0 + row];
                    const size_t ro = (size_t)(pm0 + row) * HID + pn0 + hh * 64 + cf * 4;
                    if (lbl) {
                        float4 v = *(const float4*)(eps + row * 68 + cf * 4);
                        float4 pv = *(const float4*)(g_P + (size_t)(lbl - 1) * HID
                                                     + pn0 + hh * 64 + cf * 4);
                        float4 o = {v.x + pv.x, v.y + pv.y, v.z + pv.z, v.w + pv.w};
                        *(float4*)(out + ro) = o;
                    } else {
                        *(float4*)(out + ro) = *(const float4*)(tokens + ro);
                    }
                }
                __syncwarp();
            }
            MBAR_ARRIVE(MB_EFREE(pb));
        }
    }
    __syncthreads();
    if (wid == 8) TC_DEALLOC(tmem, 512);

#else  // ------------------- portable TF32 fallback (persistent) -------------------
    float (*As)[36] = (float(*)[36])(smem);
    float (*Bs)[36] = (float(*)[36])(smem + 128 * 36 * 4);
    int*   lbl_s    = (int*)(smem + 2 * 128 * 36 * 4);
    const int wm = wid >> 2, wn = wid & 3;

    for (int it = 0; ; it++) {
        const int t = bid + it * 148;
        if (t >= NTILES) break;
        const int m0 = (t / 3) * 128, base_n = (t % 3) * 256;
        __syncthreads();
        if (tid < 128) lbl_s[tid] = labels[m0 + tid];

        for (int nh = 0; nh < 2; nh++) {
            const int n0 = base_n + nh * 128;
            float acc[4][4][4];
            #pragma unroll
            for (int a = 0; a < 4; a++)
                #pragma unroll
                for (int b = 0; b < 4; b++)
                    #pragma unroll
                    for (int c = 0; c < 4; c++) acc[a][b][c] = 0.f;
            __syncthreads();

            for (int k0 = 0; k0 < HID; k0 += 32) {
                if (tid < 256) {
                    #pragma unroll
                    for (int i = 0; i < 4; i++) {
                        int idx = tid + i * 256;
                        int r = idx >> 3, c = (idx & 7) * 4;
                        float4 va = *(const float4*)(tokens + (size_t)(m0 + r) * HID + k0 + c);
                        va.x = to_tf32(va.x); va.y = to_tf32(va.y);
                        va.z = to_tf32(va.z); va.w = to_tf32(va.w);
                        *(float4*)&As[r][c] = va;
                        float4 vb = *(const float4*)(W + (size_t)(n0 + r) * HID2 + k0 + c);
                        vb.x = to_tf32(vb.x); vb.y = to_tf32(vb.y);
                        vb.z = to_tf32(vb.z); vb.w = to_tf32(vb.w);
                        *(float4*)&Bs[r][c] = vb;
                    }
                }
                __syncthreads();
                if (tid < 256) {
                    #pragma unroll
                    for (int ks = 0; ks < 4; ks++) {
                        const int cb = ks * 8 + (lane & 3);
                        float a[4][4], b[4][2];
                        #pragma unroll
                        for (int mi = 0; mi < 4; mi++) {
                            int r = wm * 64 + mi * 16 + (lane >> 2);
                            a[mi][0] = As[r][cb];     a[mi][1] = As[r + 8][cb];
                            a[mi][2] = As[r][cb + 4]; a[mi][3] = As[r + 8][cb + 4];
                        }
                        #pragma unroll
                        for (int ni = 0; ni < 4; ni++) {
                            int r = wn * 32 + ni * 8 + (lane >> 2);
                            b[ni][0] = Bs[r][cb]; b[ni][1] = Bs[r][cb + 4];
                        }
                        #pragma unroll
                        for (int mi = 0; mi < 4; mi++)
                            #pragma unroll
                            for (int ni = 0; ni < 4; ni++)
                                mma_tf32(acc[mi][ni], a[mi], b[ni]);
                    }
                }
                __syncthreads();
            }

            if (tid < 256) {
                const int gq = lane >> 2, tg = lane & 3;
                #pragma unroll
                for (int mi = 0; mi < 4; mi++) {
                    #pragma unroll
                    for (int half = 0; half < 2; half++) {
                        int r = wm * 64 + mi * 16 + gq + half * 8;
                        int lbl = lbl_s[r];
                        size_t rowOff = (size_t)(m0 + r) * HID;
                        #pragma unroll
                        for (int ni = 0; ni < 4; ni++) {
                            int gc = n0 + wn * 32 + ni * 8 + tg * 2;
                            float2 res;
                            if (lbl != 0) {
                                float2 p = *(const float2*)(&g_P[(size_t)(lbl - 1) * HID + gc]);
                                res.x = acc[mi][ni][half * 2 + 0] + p.x;
                                res.y = acc[mi][ni][half * 2 + 1] + p.y;
                            } else {
                                res = *(const float2*)(tokens + rowOff + gc);
                            }
                            *(float2*)(out + rowOff + gc) = res;
                        }
                    }
                }
            }
        }
    }
#endif
}

extern "C" void kernel_launch(void* const* d_in, const int* in_sizes, int n_in,
                              void* d_out, int out_size) {
    const float* com    = (const float*)d_in[0];   // [16,4096,768] f32
    const int*   labels = (const int*)d_in[1];     // [16,4096] int32
    const float* lf     = (const float*)d_in[2];   // [64,768] f32
    const float* mw     = (const float*)d_in[3];   // [768,1536] f32
    const float* mb     = (const float*)d_in[4];   // [768] f32
    float* out = (float*)d_out;

    cudaFuncSetAttribute(fm_main_kernel,
                         cudaFuncAttributeMaxDynamicSharedMemorySize, SMEM_TOTAL);

    asplit_kernel<<<(int)((size_t)NTOK * HID / 4 / 256), 256>>>(com);
    bsplit_kernel<<<576, 256>>>(mw);
    p_accum_kernel<<<dim3(6, KT_SPLITS), 256>>>(lf, mw);
    p_reduce_kernel<<<(NLAB * HID + 255) / 256, 256>>>(mb);
    fm_main_kernel<<<148, 288, SMEM_TOTAL>>>(com, labels, mw, out);
}